// round 8
// baseline (speedup 1.0000x reference)
#include <cuda_runtime.h>

// SSIM loss, vertical-first separable blur — hybrid:
//   V: thread-per-column, FIELD-packed f32x2 rings (i1,i2)/(i1^2+i2^2,i1*i2)
//      -> 22 FMA2/row; unpack-at-store is free (register-pair aliasing),
//      stores 4x STS.32 into scalar SoA field buffers.
//   H: R4's proven scalar path: 4 px/thread, 4 conflict-free float4 loads per
//      field, 44 imm-form FFMA/px, scalar SSIM. (best measured issue eff.)
// Inputs: 2x [16,3,512,512] fp32. Output: 1 fp32 scalar.

typedef unsigned long long ull;

#define NTHR    160
#define TILE_W  128
#define TILE_H  16
#define RAD     5
#define KW      11
#define VCOLS   (TILE_W + 2 * RAD)   // 138
#define VSTRIDE 140                  // floats per row, 16B aligned
#define HH      512
#define WW      512
#define PLANES  48
#define GX      (WW / TILE_W)        // 4
#define GY      (HH / TILE_H)        // 32
#define NBLK    (GX * GY * PLANES)   // 6144

__device__ float        g_partials[NBLK];
__device__ unsigned int g_count = 0;

// Gaussian(sigma=1.5) 11 taps, normalized.
__device__ __forceinline__ constexpr float GW(int k) {
    return (k == 0 || k == 10) ? 0.00102838f
         : (k == 1 || k == 9)  ? 0.00759877f
         : (k == 2 || k == 8)  ? 0.03600075f
         : (k == 3 || k == 7)  ? 0.10936082f
         : (k == 4 || k == 6)  ? 0.21300554f
         :                       0.26601172f;
}

// ---- f32x2 helpers ----
__device__ __forceinline__ ull F2(float a, float b) {
    ull r; asm("mov.b64 %0,{%1,%2};" : "=l"(r) : "f"(a), "f"(b)); return r;
}
__device__ __forceinline__ void UF2(ull v, float& a, float& b) {
    asm("mov.b64 {%0,%1},%2;" : "=f"(a), "=f"(b) : "l"(v));
}
__device__ __forceinline__ ull FMA2(ull a, ull b, ull c) {
    ull r; asm("fma.rn.f32x2 %0,%1,%2,%3;" : "=l"(r) : "l"(a), "l"(b), "l"(c)); return r;
}

__global__ void __launch_bounds__(NTHR, 5)
ssim_main(const float* __restrict__ img1, const float* __restrict__ img2,
          float* __restrict__ out)
{
    // Scalar SoA field buffers (same as R4): [field][row][col].
    __shared__ __align__(16) float smf[4][TILE_H][VSTRIDE];

    const int tid   = threadIdx.x;
    const int x0    = blockIdx.x * TILE_W;
    const int y0    = blockIdx.y * TILE_H;
    const int plane = blockIdx.z;
    const size_t pbase = (size_t)plane * (HH * WW);

    // ============ Vertical phase: field-packed f32x2 rings ============
    if (tid < VCOLS) {
        ull w2[6];
        #pragma unroll
        for (int k = 0; k < 6; ++k) w2[k] = F2(GW(k), GW(k));
        const ull ONE2 = F2(1.f, 1.f);

        const int gx  = x0 + tid - RAD;
        const bool vx = ((unsigned)gx < WW);
        const int gxc = min(max(gx, 0), WW - 1);
        const float* __restrict__ p1 = img1 + pbase + gxc;
        const float* __restrict__ p2 = img2 + pbase + gxc;

        ull rab[KW];   // (i1, i2)
        ull rsp[KW];   // (i1^2+i2^2, i1*i2)
        float ca, cb;

        auto loadrow = [&](int i, float& a, float& b) {
            int gy = y0 + i - RAD;
            bool ok = vx && ((unsigned)gy < HH);
            int gyc = min(max(gy, 0), HH - 1);
            size_t off = (size_t)gyc * WW;
            a = ok ? __ldg(p1 + off) : 0.f;
            b = ok ? __ldg(p2 + off) : 0.f;
        };

        #pragma unroll
        for (int i = 0; i < KW - 1; ++i) {
            float a, b; loadrow(i, a, b);
            rab[i] = F2(a, b);
            rsp[i] = F2(fmaf(a, a, b * b), a * b);
        }
        loadrow(KW - 1, ca, cb);

        #pragma unroll
        for (int u = 0; u < TILE_H; ++u) {
            const int sl = (u + KW - 1) % KW;
            rab[sl] = F2(ca, cb);
            rsp[sl] = F2(fmaf(ca, ca, cb * cb), ca * cb);
            if (u < TILE_H - 1) loadrow(u + KW, ca, cb);

            ull ma = 0, mb = 0, qa = 0, qb = 0;   // dual chains
            #pragma unroll
            for (int j = 0; j < KW; ++j) {
                const int s = (u + j) % KW;            // compile-time
                const ull wj = w2[(j < 6) ? j : 10 - j];
                if (j & 1) { mb = FMA2(wj, rab[s], mb); qb = FMA2(wj, rsp[s], qb); }
                else       { ma = FMA2(wj, rab[s], ma); qa = FMA2(wj, rsp[s], qa); }
            }
            ull m = FMA2(ONE2, ma, mb);
            ull q = FMA2(ONE2, qa, qb);
            float m1, m2, qs, q12;
            UF2(m, m1, m2);    // free: register-pair halves
            UF2(q, qs, q12);
            smf[0][u][tid] = m1;
            smf[1][u][tid] = m2;
            smf[2][u][tid] = qs;
            smf[3][u][tid] = q12;
        }
    }
    __syncthreads();

    // ============ Horizontal + SSIM: R4's proven scalar path ============
    float acc = 0.f;
    if (tid < 128) {
        const int cg = tid & 31;    // output cols 4cg..4cg+3
        const int rg = tid >> 5;    // row slot

        #pragma unroll 1
        for (int rr = 0; rr < 4; ++rr) {
            const int r = rr * 4 + rg;

            float fm1[4], fm2[4], fqs[4], fq12[4];
            #pragma unroll
            for (int d = 0; d < 4; ++d) { fm1[d] = fm2[d] = fqs[d] = fq12[d] = 0.f; }

            #pragma unroll
            for (int f = 0; f < 4; ++f) {
                const float4* __restrict__ rp4 =
                    reinterpret_cast<const float4*>(&smf[f][r][0]);
                float4 q0 = rp4[cg + 0];
                float4 q1 = rp4[cg + 1];
                float4 q2 = rp4[cg + 2];
                float4 q3 = rp4[cg + 3];
                float cv[16] = { q0.x, q0.y, q0.z, q0.w,
                                 q1.x, q1.y, q1.z, q1.w,
                                 q2.x, q2.y, q2.z, q2.w,
                                 q3.x, q3.y, q3.z, q3.w };
                float* dst = (f == 0) ? fm1 : (f == 1) ? fm2 : (f == 2) ? fqs : fq12;
                #pragma unroll
                for (int d = 0; d < 4; ++d) {
                    float a = 0.f;
                    #pragma unroll
                    for (int k = 0; k < KW; ++k)
                        a = fmaf(GW(k), cv[d + k], a);
                    dst[d] = a;
                }
            }

            #pragma unroll
            for (int d = 0; d < 4; ++d) {
                float mu12 = fm1[d] * fm2[d];
                float mu1s = fm1[d] * fm1[d];
                float mu2s = fm2[d] * fm2[d];
                float s12  = fq12[d] - mu12;
                float n1   = fmaf(2.f, mu12, 1e-4f);
                float n2   = fmaf(2.f, s12,  9e-4f);
                float ttv  = mu1s + mu2s;
                float d1   = ttv + 1e-4f;
                float d2   = (fqs[d] - ttv) + 9e-4f;
                acc += __fdividef(n1 * n2, d1 * d2);
            }
        }
    }

    // ================= Reduction =================
    #pragma unroll
    for (int o = 16; o; o >>= 1)
        acc += __shfl_xor_sync(0xFFFFFFFFu, acc, o);

    __shared__ float ws[NTHR / 32];
    if ((tid & 31) == 0) ws[tid >> 5] = acc;
    __syncthreads();

    const int bid = (blockIdx.z * GY + blockIdx.y) * GX + blockIdx.x;
    __shared__ unsigned int is_last;
    if (tid == 0) {
        float bs = 0.f;
        #pragma unroll
        for (int i = 0; i < NTHR / 32; ++i) bs += ws[i];
        __stcg(&g_partials[bid], bs);
        __threadfence();
        is_last = (atomicAdd(&g_count, 1u) == (unsigned)(NBLK - 1));
    }
    __syncthreads();

    if (is_last) {
        double s = 0.0;
        for (int i = tid; i < NBLK; i += NTHR)
            s += (double)__ldcg(&g_partials[i]);
        #pragma unroll
        for (int o = 16; o; o >>= 1)
            s += __shfl_xor_sync(0xFFFFFFFFu, s, o);
        __shared__ double wd[NTHR / 32];
        if ((tid & 31) == 0) wd[tid >> 5] = s;
        __syncthreads();
        if (tid == 0) {
            double bs = 0.0;
            #pragma unroll
            for (int i = 0; i < NTHR / 32; ++i) bs += wd[i];
            double n = (double)PLANES * HH * WW;
            out[0] = (float)(1.0 - bs / n);
            g_count = 0;   // reset for next graph replay
        }
    }
}

extern "C" void kernel_launch(void* const* d_in, const int* in_sizes, int n_in,
                              void* d_out, int out_size)
{
    (void)in_sizes; (void)n_in; (void)out_size;
    const float* img1 = (const float*)d_in[0];
    const float* img2 = (const float*)d_in[1];
    float* out = (float*)d_out;

    dim3 grid(GX, GY, PLANES);
    ssim_main<<<grid, NTHR>>>(img1, img2, out);
}

// round 9
// speedup vs baseline: 1.1336x; 1.1336x over previous
#include <cuda_runtime.h>

// SSIM loss, vertical-first separable blur (scalar imm-FFMA, proven R4 path):
//   V: thread-per-column vertical 11-tap of {i1,i2,i1^2+i2^2,i1*i2} from global
//      via incremental pointer walk (1 ISETP/row), register rings -> smem SoA.
//   H: 4 px/thread, conflict-free float4 smem reads, 11-tap blur + SSIM with
//      BATCHED reciprocal: 1 MUFU.RCP per 4 pixels (common-denominator tree).
// Inputs: 2x [16,3,512,512] fp32. Output: 1 fp32 scalar.

#define NTHR    160
#define TILE_W  128
#define TILE_H  16
#define RAD     5
#define KW      11
#define VCOLS   (TILE_W + 2 * RAD)   // 138
#define VSTRIDE 140                  // floats per row, 16B aligned
#define HH      512
#define WW      512
#define PLANES  48
#define GX      (WW / TILE_W)        // 4
#define GY      (HH / TILE_H)        // 32
#define NBLK    (GX * GY * PLANES)   // 6144

__device__ float        g_partials[NBLK];
__device__ unsigned int g_count = 0;

// Gaussian(sigma=1.5) 11 taps, normalized; literals -> immediate-form FFMA.
__device__ __forceinline__ constexpr float GW(int k) {
    return (k == 0 || k == 10) ? 0.00102838f
         : (k == 1 || k == 9)  ? 0.00759877f
         : (k == 2 || k == 8)  ? 0.03600075f
         : (k == 3 || k == 7)  ? 0.10936082f
         : (k == 4 || k == 6)  ? 0.21300554f
         :                       0.26601172f;
}

__global__ void __launch_bounds__(NTHR, 5)
ssim_main(const float* __restrict__ img1, const float* __restrict__ img2,
          float* __restrict__ out)
{
    // SoA field buffers: [field][row][col], rows 16B-aligned.
    __shared__ __align__(16) float smf[4][TILE_H][VSTRIDE];

    const int tid   = threadIdx.x;
    const int x0    = blockIdx.x * TILE_W;
    const int y0    = blockIdx.y * TILE_H;
    const int plane = blockIdx.z;
    const size_t pbase = (size_t)plane * (HH * WW);

    // ================= Vertical phase =================
    if (tid < VCOLS) {
        const int gx  = x0 + tid - RAD;
        const bool vx = ((unsigned)gx < WW);
        const int gxc = min(max(gx, 0), WW - 1);

        // Incremental pointer walk: ptr tracks row clamp(row), advance iff
        // both current and next row indices are in [0, HH).
        int  row = y0 - RAD;
        bool pv  = ((unsigned)row < HH);
        const float* __restrict__ q1 = img1 + pbase + gxc + (size_t)max(row, 0) * WW;
        const float* __restrict__ q2 = img2 + pbase + gxc + (size_t)max(row, 0) * WW;

        auto loadrow = [&](float& a, float& b) {
            const bool ok = vx && pv;
            a = ok ? __ldg(q1) : 0.f;
            b = ok ? __ldg(q2) : 0.f;
            const int  nrow = row + 1;
            const bool pn   = ((unsigned)nrow < HH);
            if (pv && pn) { q1 += WW; q2 += WW; }
            row = nrow; pv = pn;
        };

        float ra[KW], rb[KW], rs[KW], rp[KW];

        #pragma unroll
        for (int i = 0; i < KW - 1; ++i) {
            float a, b; loadrow(a, b);
            ra[i] = a; rb[i] = b;
            rs[i] = fmaf(b, b, a * a);
            rp[i] = a * b;
        }
        float ca, cb;
        loadrow(ca, cb);   // row index 10

        #pragma unroll
        for (int u = 0; u < TILE_H; ++u) {
            const int sl = (u + KW - 1) % KW;
            ra[sl] = ca; rb[sl] = cb;
            rs[sl] = fmaf(cb, cb, ca * ca);
            rp[sl] = ca * cb;
            if (u < TILE_H - 1) loadrow(ca, cb);   // prefetch next row

            float m1 = 0.f, m2 = 0.f, qs = 0.f, q12 = 0.f;
            #pragma unroll
            for (int j = 0; j < KW; ++j) {
                const int s = (u + j) % KW;      // compile-time
                m1  = fmaf(GW(j), ra[s], m1);
                m2  = fmaf(GW(j), rb[s], m2);
                qs  = fmaf(GW(j), rs[s], qs);
                q12 = fmaf(GW(j), rp[s], q12);
            }
            smf[0][u][tid] = m1;
            smf[1][u][tid] = m2;
            smf[2][u][tid] = qs;
            smf[3][u][tid] = q12;
        }
    }
    __syncthreads();

    // ================= Horizontal + SSIM phase =================
    float acc = 0.f;
    if (tid < 128) {
        const int cg = tid & 31;    // output cols 4cg..4cg+3
        const int rg = tid >> 5;    // row slot

        #pragma unroll 1
        for (int rr = 0; rr < 4; ++rr) {
            const int r = rr * 4 + rg;

            float fm1[4], fm2[4], fqs[4], fq12[4];
            #pragma unroll
            for (int d = 0; d < 4; ++d) { fm1[d] = fm2[d] = fqs[d] = fq12[d] = 0.f; }

            // Per field: 4 float4 loads cover cols 4cg..4cg+15 (need ..+13).
            #pragma unroll
            for (int f = 0; f < 4; ++f) {
                const float4* __restrict__ rp4 =
                    reinterpret_cast<const float4*>(&smf[f][r][0]);
                float4 q0 = rp4[cg + 0];
                float4 q1 = rp4[cg + 1];
                float4 q2 = rp4[cg + 2];
                float4 q3 = rp4[cg + 3];
                float cv[16] = { q0.x, q0.y, q0.z, q0.w,
                                 q1.x, q1.y, q1.z, q1.w,
                                 q2.x, q2.y, q2.z, q2.w,
                                 q3.x, q3.y, q3.z, q3.w };
                float* dst = (f == 0) ? fm1 : (f == 1) ? fm2 : (f == 2) ? fqs : fq12;
                #pragma unroll
                for (int d = 0; d < 4; ++d) {
                    float a = 0.f;
                    #pragma unroll
                    for (int k = 0; k < KW; ++k)
                        a = fmaf(GW(k), cv[d + k], a);
                    dst[d] = a;
                }
            }

            // SSIM numerators/denominators per pixel, then ONE reciprocal
            // for all 4 pixels via common-denominator combination.
            float nn[4], dd[4];
            #pragma unroll
            for (int d = 0; d < 4; ++d) {
                float mu12 = fm1[d] * fm2[d];
                float mu1s = fm1[d] * fm1[d];
                float mu2s = fm2[d] * fm2[d];
                float s12  = fq12[d] - mu12;
                float n1   = fmaf(2.f, mu12, 1e-4f);
                float n2   = fmaf(2.f, s12,  9e-4f);
                float ttv  = mu1s + mu2s;
                float d1   = ttv + 1e-4f;
                float d2   = (fqs[d] - ttv) + 9e-4f;
                nn[d] = n1 * n2;
                dd[d] = d1 * d2;
            }
            float D01 = dd[0] * dd[1];
            float D23 = dd[2] * dd[3];
            float r01 = fmaf(nn[0], dd[1], nn[1] * dd[0]);
            float r23 = fmaf(nn[2], dd[3], nn[3] * dd[2]);
            float Rn  = fmaf(r01, D23, r23 * D01);
            float Dn  = D01 * D23;
            acc += __fdividef(Rn, Dn);   // 1 MUFU.RCP per 4 pixels
        }
    }

    // ================= Reduction =================
    #pragma unroll
    for (int o = 16; o; o >>= 1)
        acc += __shfl_xor_sync(0xFFFFFFFFu, acc, o);

    __shared__ float ws[NTHR / 32];
    if ((tid & 31) == 0) ws[tid >> 5] = acc;
    __syncthreads();

    const int bid = (blockIdx.z * GY + blockIdx.y) * GX + blockIdx.x;
    __shared__ unsigned int is_last;
    if (tid == 0) {
        float bs = 0.f;
        #pragma unroll
        for (int i = 0; i < NTHR / 32; ++i) bs += ws[i];
        __stcg(&g_partials[bid], bs);
        __threadfence();
        is_last = (atomicAdd(&g_count, 1u) == (unsigned)(NBLK - 1));
    }
    __syncthreads();

    if (is_last) {
        double s = 0.0;
        for (int i = tid; i < NBLK; i += NTHR)
            s += (double)__ldcg(&g_partials[i]);
        #pragma unroll
        for (int o = 16; o; o >>= 1)
            s += __shfl_xor_sync(0xFFFFFFFFu, s, o);
        __shared__ double wd[NTHR / 32];
        if ((tid & 31) == 0) wd[tid >> 5] = s;
        __syncthreads();
        if (tid == 0) {
            double bs = 0.0;
            #pragma unroll
            for (int i = 0; i < NTHR / 32; ++i) bs += wd[i];
            double n = (double)PLANES * HH * WW;
            out[0] = (float)(1.0 - bs / n);
            g_count = 0;   // reset for next graph replay
        }
    }
}

extern "C" void kernel_launch(void* const* d_in, const int* in_sizes, int n_in,
                              void* d_out, int out_size)
{
    (void)in_sizes; (void)n_in; (void)out_size;
    const float* img1 = (const float*)d_in[0];
    const float* img2 = (const float*)d_in[1];
    float* out = (float*)d_out;

    dim3 grid(GX, GY, PLANES);
    ssim_main<<<grid, NTHR>>>(img1, img2, out);
}

// round 10
// speedup vs baseline: 1.1435x; 1.0087x over previous
#include <cuda_runtime.h>

// SSIM loss, vertical-first separable blur (R4 structure, occupancy-tuned):
//   V: thread-per-column vertical 11-tap of {i1,i2,i1^2+i2^2,i1*i2}
//      from GLOBAL (register rings, insert-time squares), -> smem SoA
//   H: 4 adjacent px/thread, float4 conflict-free smem reads,
//      horizontal 11-tap + SSIM + deterministic mean (fused last-block).
//   launch_bounds(160,6): 6 blocks/SM (30 warps, 46.9% occ), regs capped 68.
// Inputs: 2x [16,3,512,512] fp32. Output: 1 fp32 scalar.

#define NTHR    160
#define TILE_W  128
#define TILE_H  16
#define RAD     5
#define KW      11
#define VCOLS   (TILE_W + 2 * RAD)   // 138
#define VSTRIDE 140                  // floats per row, 16B aligned
#define HH      512
#define WW      512
#define PLANES  48
#define GX      (WW / TILE_W)        // 4
#define GY      (HH / TILE_H)        // 32
#define NBLK    (GX * GY * PLANES)   // 6144

__device__ float        g_partials[NBLK];
__device__ unsigned int g_count = 0;

// Gaussian(sigma=1.5) 11 taps, normalized; literals -> immediate-form FFMA.
__device__ __forceinline__ constexpr float GW(int k) {
    return (k == 0 || k == 10) ? 0.00102838f
         : (k == 1 || k == 9)  ? 0.00759877f
         : (k == 2 || k == 8)  ? 0.03600075f
         : (k == 3 || k == 7)  ? 0.10936082f
         : (k == 4 || k == 6)  ? 0.21300554f
         :                       0.26601172f;
}

__global__ void __launch_bounds__(NTHR, 6)
ssim_main(const float* __restrict__ img1, const float* __restrict__ img2,
          float* __restrict__ out)
{
    // SoA field buffers: [field][row][col], rows 16B-aligned.
    __shared__ __align__(16) float smf[4][TILE_H][VSTRIDE];

    const int tid   = threadIdx.x;
    const int x0    = blockIdx.x * TILE_W;
    const int y0    = blockIdx.y * TILE_H;
    const int plane = blockIdx.z;
    const size_t pbase = (size_t)plane * (HH * WW);

    // ================= Vertical phase =================
    if (tid < VCOLS) {
        const int gx  = x0 + tid - RAD;
        const bool vx = ((unsigned)gx < WW);
        const int gxc = min(max(gx, 0), WW - 1);
        const float* __restrict__ p1 = img1 + pbase + gxc;
        const float* __restrict__ p2 = img2 + pbase + gxc;

        float ra[KW], rb[KW], rs[KW], rp[KW];

        auto loadrow = [&](int i, float& a, float& b) {
            int gy = y0 + i - RAD;
            bool ok = vx && ((unsigned)gy < HH);
            int gyc = min(max(gy, 0), HH - 1);
            size_t off = (size_t)gyc * WW;
            a = ok ? __ldg(p1 + off) : 0.f;
            b = ok ? __ldg(p2 + off) : 0.f;
        };

        #pragma unroll
        for (int i = 0; i < KW - 1; ++i) {
            float a, b; loadrow(i, a, b);
            ra[i] = a; rb[i] = b;
            rs[i] = fmaf(b, b, a * a);
            rp[i] = a * b;
        }
        float ca, cb;
        loadrow(KW - 1, ca, cb);   // row index 10

        #pragma unroll
        for (int u = 0; u < TILE_H; ++u) {
            const int sl = (u + KW - 1) % KW;
            ra[sl] = ca; rb[sl] = cb;
            rs[sl] = fmaf(cb, cb, ca * ca);
            rp[sl] = ca * cb;
            if (u < TILE_H - 1) loadrow(u + KW, ca, cb);   // prefetch next row

            float m1 = 0.f, m2 = 0.f, qs = 0.f, q12 = 0.f;
            #pragma unroll
            for (int j = 0; j < KW; ++j) {
                const int s = (u + j) % KW;      // compile-time
                m1  = fmaf(GW(j), ra[s], m1);
                m2  = fmaf(GW(j), rb[s], m2);
                qs  = fmaf(GW(j), rs[s], qs);
                q12 = fmaf(GW(j), rp[s], q12);
            }
            smf[0][u][tid] = m1;
            smf[1][u][tid] = m2;
            smf[2][u][tid] = qs;
            smf[3][u][tid] = q12;
        }
    }
    __syncthreads();

    // ================= Horizontal + SSIM phase =================
    float acc = 0.f;
    if (tid < 128) {
        const int cg = tid & 31;    // output cols 4cg..4cg+3
        const int rg = tid >> 5;    // row slot

        #pragma unroll 1
        for (int rr = 0; rr < 4; ++rr) {
            const int r = rr * 4 + rg;

            float fm1[4], fm2[4], fqs[4], fq12[4];
            #pragma unroll
            for (int d = 0; d < 4; ++d) { fm1[d] = fm2[d] = fqs[d] = fq12[d] = 0.f; }

            // Per field: 4 float4 loads cover cols 4cg..4cg+15 (need ..+13).
            #pragma unroll
            for (int f = 0; f < 4; ++f) {
                const float4* __restrict__ rp4 =
                    reinterpret_cast<const float4*>(&smf[f][r][0]);
                float4 q0 = rp4[cg + 0];
                float4 q1 = rp4[cg + 1];
                float4 q2 = rp4[cg + 2];
                float4 q3 = rp4[cg + 3];
                float cv[16] = { q0.x, q0.y, q0.z, q0.w,
                                 q1.x, q1.y, q1.z, q1.w,
                                 q2.x, q2.y, q2.z, q2.w,
                                 q3.x, q3.y, q3.z, q3.w };
                float* dst = (f == 0) ? fm1 : (f == 1) ? fm2 : (f == 2) ? fqs : fq12;
                #pragma unroll
                for (int d = 0; d < 4; ++d) {
                    float a = 0.f;
                    #pragma unroll
                    for (int k = 0; k < KW; ++k)
                        a = fmaf(GW(k), cv[d + k], a);
                    dst[d] = a;
                }
            }

            #pragma unroll
            for (int d = 0; d < 4; ++d) {
                float mu12 = fm1[d] * fm2[d];
                float mu1s = fm1[d] * fm1[d];
                float mu2s = fm2[d] * fm2[d];
                float s12  = fq12[d] - mu12;
                float n1   = fmaf(2.f, mu12, 1e-4f);
                float n2   = fmaf(2.f, s12,  9e-4f);
                float ttv  = mu1s + mu2s;
                float d1   = ttv + 1e-4f;
                float d2   = (fqs[d] - ttv) + 9e-4f;
                acc += __fdividef(n1 * n2, d1 * d2);
            }
        }
    }

    // ================= Reduction =================
    #pragma unroll
    for (int o = 16; o; o >>= 1)
        acc += __shfl_xor_sync(0xFFFFFFFFu, acc, o);

    __shared__ float ws[NTHR / 32];
    if ((tid & 31) == 0) ws[tid >> 5] = acc;
    __syncthreads();

    const int bid = (blockIdx.z * GY + blockIdx.y) * GX + blockIdx.x;
    __shared__ unsigned int is_last;
    if (tid == 0) {
        float bs = 0.f;
        #pragma unroll
        for (int i = 0; i < NTHR / 32; ++i) bs += ws[i];
        __stcg(&g_partials[bid], bs);
        __threadfence();
        is_last = (atomicAdd(&g_count, 1u) == (unsigned)(NBLK - 1));
    }
    __syncthreads();

    if (is_last) {
        double s = 0.0;
        for (int i = tid; i < NBLK; i += NTHR)
            s += (double)__ldcg(&g_partials[i]);
        #pragma unroll
        for (int o = 16; o; o >>= 1)
            s += __shfl_xor_sync(0xFFFFFFFFu, s, o);
        __shared__ double wd[NTHR / 32];
        if ((tid & 31) == 0) wd[tid >> 5] = s;
        __syncthreads();
        if (tid == 0) {
            double bs = 0.0;
            #pragma unroll
            for (int i = 0; i < NTHR / 32; ++i) bs += wd[i];
            double n = (double)PLANES * HH * WW;
            out[0] = (float)(1.0 - bs / n);
            g_count = 0;   // reset for next graph replay
        }
    }
}

extern "C" void kernel_launch(void* const* d_in, const int* in_sizes, int n_in,
                              void* d_out, int out_size)
{
    (void)in_sizes; (void)n_in; (void)out_size;
    const float* img1 = (const float*)d_in[0];
    const float* img2 = (const float*)d_in[1];
    float* out = (float*)d_out;

    dim3 grid(GX, GY, PLANES);
    ssim_main<<<grid, NTHR>>>(img1, img2, out);
}